// round 1
// baseline (speedup 1.0000x reference)
#include <cuda_runtime.h>
#include <math.h>

// Problem constants: B=32, C=32, H=64, W=64, pool k=2 -> H2=W2=32.
// Grid: 1024 blocks, one per (c, h2). Block: 1024 threads = (i in [0,32)) x (w2 in [0,32)).

__device__ double g_acc;

__global__ void k_zero() { g_acc = 0.0; }

__global__ __launch_bounds__(1024) void k_main(
    const float* __restrict__ mu_a, const float* __restrict__ lv_a,
    const float* __restrict__ mu_b, const float* __restrict__ lv_b)
{
    __shared__ float s_ma[32 * 33];
    __shared__ float s_va[32 * 33];
    __shared__ float s_mb[32 * 33];
    __shared__ float s_vb[32 * 33];
    __shared__ double s_wsum[32];

    const int t  = threadIdx.x;
    const int i  = t >> 5;      // batch index
    const int w2 = t & 31;      // pooled column
    const int c  = blockIdx.x >> 5;
    const int h2 = blockIdx.x & 31;

    // element index of (i, c, 2*h2, 2*w2) in a (32,32,64,64) tensor
    const int base = ((i * 32 + c) * 64 + 2 * h2) * 64 + 2 * w2;

    // Phase 1: fused 2x2 avgpool (+ exp for variances)
    float2 a0  = *(const float2*)(mu_a + base);
    float2 a1  = *(const float2*)(mu_a + base + 64);
    float2 la0 = *(const float2*)(lv_a + base);
    float2 la1 = *(const float2*)(lv_a + base + 64);
    float2 b0  = *(const float2*)(mu_b + base);
    float2 b1  = *(const float2*)(mu_b + base + 64);
    float2 lb0 = *(const float2*)(lv_b + base);
    float2 lb1 = *(const float2*)(lv_b + base + 64);

    float ma = (a0.x + a0.y + a1.x + a1.y) * 0.25f;
    float va = (expf(la0.x) + expf(la0.y) + expf(la1.x) + expf(la1.y)) * 0.0625f; // avg/4 = sum/16
    float mb = (b0.x + b0.y + b1.x + b1.y) * 0.25f;
    float vb = (expf(lb0.x) + expf(lb0.y) + expf(lb1.x) + expf(lb1.y)) * 0.0625f;

    s_ma[i * 33 + w2] = ma;
    s_va[i * 33 + w2] = va;
    s_mb[i * 33 + w2] = mb;
    s_vb[i * 33 + w2] = vb;
    __syncthreads();

    // Phase 2: warp (t>>5) owns pooled position w2p; lane = j (batch index).
    const int j   = t & 31;
    const int w2p = t >> 5;
    float maj = s_ma[j * 33 + w2p];
    float vaj = s_va[j * 33 + w2p];
    float mbj = s_mb[j * 33 + w2p];
    float vbj = s_vb[j * 33 + w2p];

    // Batch sums over i (same values as j-lane values -> reuse)
    float Sm = maj, Sm2 = maj * maj, Sv2 = vaj * vaj;
    #pragma unroll
    for (int o = 16; o; o >>= 1) {
        Sm  += __shfl_xor_sync(0xffffffffu, Sm,  o);
        Sm2 += __shfl_xor_sync(0xffffffffu, Sm2, o);
        Sv2 += __shfl_xor_sync(0xffffffffu, Sv2, o);
    }

    const float s2pi = 2.5066282746310002f; // sqrt(2*pi)
    float la = logf(1.0f / (vaj * s2pi) + 1e-6f);
    float lb = logf(1.0f / (vbj * s2pi) + 1e-6f);
    // sum_i (va_i^2 + (ma_i - x_j)^2) = Sv2 + Sm2 - 2 x_j Sm + B x_j^2
    float na = Sv2 + Sm2 - 2.0f * maj * Sm + 32.0f * maj * maj;
    float nb = Sv2 + Sm2 - 2.0f * mbj * Sm + 32.0f * mbj * mbj;
    float d  = 32.0f * (la - lb) - na / (2.0f * vaj * vaj) + nb / (2.0f * vbj * vbj);

    #pragma unroll
    for (int o = 16; o; o >>= 1)
        d += __shfl_xor_sync(0xffffffffu, d, o);

    if (j == 0) s_wsum[w2p] = (double)d;
    __syncthreads();
    if (t == 0) {
        double s = 0.0;
        #pragma unroll
        for (int w = 0; w < 32; w++) s += s_wsum[w];
        atomicAdd(&g_acc, s);
    }
}

__global__ void k_final(float* out) {
    out[0] = (float)(g_acc * (1.0 / 1024.0)); // / (B*B)
}

extern "C" void kernel_launch(void* const* d_in, const int* in_sizes, int n_in,
                              void* d_out, int out_size) {
    const float* mu_a = (const float*)d_in[0];
    const float* lv_a = (const float*)d_in[1];
    const float* mu_b = (const float*)d_in[2];
    const float* lv_b = (const float*)d_in[3];

    k_zero<<<1, 1>>>();
    k_main<<<1024, 1024>>>(mu_a, lv_a, mu_b, lv_b);
    k_final<<<1, 1>>>((float*)d_out);
}

// round 3
// speedup vs baseline: 1.0777x; 1.0777x over previous
#include <cuda_runtime.h>
#include <math.h>

// Problem constants: B=32, C=32, H=64, W=64, pool k=2 -> H2=W2=32.
// Grid: 1024 blocks, one per (c, h2). Block: 1024 threads = (i in [0,32)) x (w2 in [0,32)).
// Single fused kernel: pool + closed-form pairwise reduction + last-block finalize.

__device__ double g_part[1024];
__device__ unsigned int g_count = 0;   // self-resetting: last block sets it back to 0

__global__ __launch_bounds__(1024) void k_main(
    const float* __restrict__ mu_a, const float* __restrict__ lv_a,
    const float* __restrict__ mu_b, const float* __restrict__ lv_b,
    float* __restrict__ out)
{
    __shared__ float s_ma[32 * 33];
    __shared__ float s_va[32 * 33];
    __shared__ float s_mb[32 * 33];
    __shared__ float s_vb[32 * 33];
    __shared__ double s_wsum[32];
    __shared__ bool  s_last;

    const int t  = threadIdx.x;
    const int i  = t >> 5;      // batch index
    const int w2 = t & 31;      // pooled column
    const int c  = blockIdx.x >> 5;
    const int h2 = blockIdx.x & 31;

    // element index of (i, c, 2*h2, 2*w2) in a (32,32,64,64) tensor
    const int base = ((i * 32 + c) * 64 + 2 * h2) * 64 + 2 * w2;

    // Phase 1: fused 2x2 avgpool (+ exp for variances)
    float2 a0  = *(const float2*)(mu_a + base);
    float2 a1  = *(const float2*)(mu_a + base + 64);
    float2 la0 = *(const float2*)(lv_a + base);
    float2 la1 = *(const float2*)(lv_a + base + 64);
    float2 b0  = *(const float2*)(mu_b + base);
    float2 b1  = *(const float2*)(mu_b + base + 64);
    float2 lb0 = *(const float2*)(lv_b + base);
    float2 lb1 = *(const float2*)(lv_b + base + 64);

    float ma = (a0.x + a0.y + a1.x + a1.y) * 0.25f;
    float va = (__expf(la0.x) + __expf(la0.y) + __expf(la1.x) + __expf(la1.y)) * 0.0625f;
    float mb = (b0.x + b0.y + b1.x + b1.y) * 0.25f;
    float vb = (__expf(lb0.x) + __expf(lb0.y) + __expf(lb1.x) + __expf(lb1.y)) * 0.0625f;

    s_ma[i * 33 + w2] = ma;
    s_va[i * 33 + w2] = va;
    s_mb[i * 33 + w2] = mb;
    s_vb[i * 33 + w2] = vb;
    __syncthreads();

    // Phase 2: warp (t>>5) owns pooled position w2p; lane = j (batch index).
    const int j   = t & 31;
    const int w2p = t >> 5;
    float maj = s_ma[j * 33 + w2p];
    float vaj = s_va[j * 33 + w2p];
    float mbj = s_mb[j * 33 + w2p];
    float vbj = s_vb[j * 33 + w2p];

    // Batch sums over i (lane values ARE the i-values for this position)
    float Sm = maj, Sm2 = maj * maj, Sv2 = vaj * vaj;
    #pragma unroll
    for (int o = 16; o; o >>= 1) {
        Sm  += __shfl_xor_sync(0xffffffffu, Sm,  o);
        Sm2 += __shfl_xor_sync(0xffffffffu, Sm2, o);
        Sv2 += __shfl_xor_sync(0xffffffffu, Sv2, o);
    }

    const float s2pi = 2.5066282746310002f; // sqrt(2*pi)
    float la = __logf(1.0f / (vaj * s2pi) + 1e-6f);
    float lb = __logf(1.0f / (vbj * s2pi) + 1e-6f);
    // sum_i (va_i^2 + (ma_i - x_j)^2) = Sv2 + Sm2 - 2 x_j Sm + B x_j^2
    float na = Sv2 + Sm2 - 2.0f * maj * Sm + 32.0f * maj * maj;
    float nb = Sv2 + Sm2 - 2.0f * mbj * Sm + 32.0f * mbj * mbj;
    float d  = 32.0f * (la - lb) - na / (2.0f * vaj * vaj) + nb / (2.0f * vbj * vbj);

    #pragma unroll
    for (int o = 16; o; o >>= 1)
        d += __shfl_xor_sync(0xffffffffu, d, o);

    if (j == 0) s_wsum[w2p] = (double)d;
    __syncthreads();

    // Block partial -> global, then last-block finalize (self-resetting counter)
    if (t == 0) {
        double s = 0.0;
        #pragma unroll
        for (int w = 0; w < 32; w++) s += s_wsum[w];
        g_part[blockIdx.x] = s;
        __threadfence();
        unsigned int prev = atomicInc(&g_count, 0xffffffffu);
        s_last = (prev == gridDim.x - 1);
    }
    __syncthreads();

    if (s_last) {
        // 1024 threads: each reads one partial, tree-reduce in double.
        double v = g_part[t];
        #pragma unroll
        for (int o = 16; o; o >>= 1)
            v += __shfl_xor_sync(0xffffffffu, v, o);
        __shared__ double s_fin[32];
        if ((t & 31) == 0) s_fin[t >> 5] = v;
        __syncthreads();
        if (t == 0) {
            double s = 0.0;
            #pragma unroll
            for (int w = 0; w < 32; w++) s += s_fin[w];
            out[0] = (float)(s * (1.0 / 1024.0));   // / (B*B)
            g_count = 0;                            // reset for next graph replay
        }
    }
}

extern "C" void kernel_launch(void* const* d_in, const int* in_sizes, int n_in,
                              void* d_out, int out_size) {
    const float* mu_a = (const float*)d_in[0];
    const float* lv_a = (const float*)d_in[1];
    const float* mu_b = (const float*)d_in[2];
    const float* lv_b = (const float*)d_in[3];

    k_main<<<1024, 1024>>>(mu_a, lv_a, mu_b, lv_b, (float*)d_out);
}

// round 5
// speedup vs baseline: 1.2811x; 1.1888x over previous
#include <cuda_runtime.h>
#include <math.h>

// B=32, C=32, H=64, W=64, pool k=2 -> 32x32 pooled.
// Grid: 2048 blocks = (c, h2, half). Block: 256 threads = (i in [0,32)) x (p in [0,8)).
// Each thread pools 2 cells (float4 over 2 rows) for all 4 tensors.

__device__ double g_part[2048];
__device__ unsigned int g_count = 0;   // self-resetting

__global__ __launch_bounds__(256) void k_main(
    const float* __restrict__ mu_a, const float* __restrict__ lv_a,
    const float* __restrict__ mu_b, const float* __restrict__ lv_b,
    float* __restrict__ out)
{
    __shared__ float s_ma[32 * 17];
    __shared__ float s_va[32 * 17];
    __shared__ float s_mb[32 * 17];
    __shared__ float s_vb[32 * 17];
    __shared__ double s_wsum[8];
    __shared__ bool  s_last;

    const int t    = threadIdx.x;
    const int i    = t >> 3;          // batch index 0..31
    const int p    = t & 7;           // w2-pair index 0..7
    const int b    = blockIdx.x;
    const int c    = b >> 6;
    const int h2   = (b >> 1) & 31;
    const int half = b & 1;           // which 16 w2 columns

    // element (i, c, 2*h2, half*32 + 4*p)
    const int base = ((i * 32 + c) * 64 + 2 * h2) * 64 + half * 32 + 4 * p;

    // 8 independent float4 loads (front-batched for MLP)
    float4 A0 = *(const float4*)(mu_a + base);
    float4 A1 = *(const float4*)(mu_a + base + 64);
    float4 La0 = *(const float4*)(lv_a + base);
    float4 La1 = *(const float4*)(lv_a + base + 64);
    float4 B0 = *(const float4*)(mu_b + base);
    float4 B1 = *(const float4*)(mu_b + base + 64);
    float4 Lb0 = *(const float4*)(lv_b + base);
    float4 Lb1 = *(const float4*)(lv_b + base + 64);

    // Pool: cell0 = components (x,y), cell1 = (z,w); var = avg(exp)/4 = sum(exp)/16
    float ma0 = (A0.x + A0.y + A1.x + A1.y) * 0.25f;
    float ma1 = (A0.z + A0.w + A1.z + A1.w) * 0.25f;
    float va0 = (__expf(La0.x) + __expf(La0.y) + __expf(La1.x) + __expf(La1.y)) * 0.0625f;
    float va1 = (__expf(La0.z) + __expf(La0.w) + __expf(La1.z) + __expf(La1.w)) * 0.0625f;
    float mb0 = (B0.x + B0.y + B1.x + B1.y) * 0.25f;
    float mb1 = (B0.z + B0.w + B1.z + B1.w) * 0.25f;
    float vb0 = (__expf(Lb0.x) + __expf(Lb0.y) + __expf(Lb1.x) + __expf(Lb1.y)) * 0.0625f;
    float vb1 = (__expf(Lb0.z) + __expf(Lb0.w) + __expf(Lb1.z) + __expf(Lb1.w)) * 0.0625f;

    const int w0 = 2 * p;             // local pooled column 0..15
    s_ma[i * 17 + w0] = ma0;  s_ma[i * 17 + w0 + 1] = ma1;
    s_va[i * 17 + w0] = va0;  s_va[i * 17 + w0 + 1] = va1;
    s_mb[i * 17 + w0] = mb0;  s_mb[i * 17 + w0 + 1] = mb1;
    s_vb[i * 17 + w0] = vb0;  s_vb[i * 17 + w0 + 1] = vb1;
    __syncthreads();

    // Phase 2: 8 warps; warp wid handles local columns 2*wid and 2*wid+1; lane = j.
    const int j   = t & 31;
    const int wid = t >> 5;
    double dsum = 0.0;
    const float s2pi = 2.5066282746310002f;

    #pragma unroll
    for (int cell = 0; cell < 2; cell++) {
        const int w = 2 * wid + cell;
        float maj = s_ma[j * 17 + w];
        float vaj = s_va[j * 17 + w];
        float mbj = s_mb[j * 17 + w];
        float vbj = s_vb[j * 17 + w];

        float Sm = maj, Sm2 = maj * maj, Sv2 = vaj * vaj;
        #pragma unroll
        for (int o = 16; o; o >>= 1) {
            Sm  += __shfl_xor_sync(0xffffffffu, Sm,  o);
            Sm2 += __shfl_xor_sync(0xffffffffu, Sm2, o);
            Sv2 += __shfl_xor_sync(0xffffffffu, Sv2, o);
        }

        float la = __logf(1.0f / (vaj * s2pi) + 1e-6f);
        float lb = __logf(1.0f / (vbj * s2pi) + 1e-6f);
        float na = Sv2 + Sm2 - 2.0f * maj * Sm + 32.0f * maj * maj;
        float nb = Sv2 + Sm2 - 2.0f * mbj * Sm + 32.0f * mbj * mbj;
        float d  = 32.0f * (la - lb) - na / (2.0f * vaj * vaj) + nb / (2.0f * vbj * vbj);

        #pragma unroll
        for (int o = 16; o; o >>= 1)
            d += __shfl_xor_sync(0xffffffffu, d, o);
        dsum += (double)d;
    }

    if (j == 0) s_wsum[wid] = dsum;
    __syncthreads();

    if (t == 0) {
        double s = 0.0;
        #pragma unroll
        for (int w = 0; w < 8; w++) s += s_wsum[w];
        g_part[b] = s;
        __threadfence();
        unsigned int prev = atomicInc(&g_count, 0xffffffffu);
        s_last = (prev == gridDim.x - 1);
    }
    __syncthreads();

    if (s_last) {
        // 256 threads reduce 2048 partials: 8 each, then tree.
        double v = 0.0;
        #pragma unroll
        for (int k = 0; k < 8; k++) v += g_part[t + 256 * k];
        #pragma unroll
        for (int o = 16; o; o >>= 1)
            v += __shfl_xor_sync(0xffffffffu, v, o);
        __shared__ double s_fin[8];
        if ((t & 31) == 0) s_fin[t >> 5] = v;
        __syncthreads();
        if (t == 0) {
            double s = 0.0;
            #pragma unroll
            for (int w = 0; w < 8; w++) s += s_fin[w];
            out[0] = (float)(s * (1.0 / 1024.0));   // / (B*B)
            g_count = 0;                            // reset for next replay
        }
    }
}

extern "C" void kernel_launch(void* const* d_in, const int* in_sizes, int n_in,
                              void* d_out, int out_size) {
    const float* mu_a = (const float*)d_in[0];
    const float* lv_a = (const float*)d_in[1];
    const float* mu_b = (const float*)d_in[2];
    const float* lv_b = (const float*)d_in[3];

    k_main<<<2048, 256>>>(mu_a, lv_a, mu_b, lv_b, (float*)d_out);
}